// round 8
// baseline (speedup 1.0000x reference)
#include <cuda_runtime.h>
#include <math.h>

#define BB 64
#define FF 512
#define EE 256
#define HH 8
#define DD 32
#define LL 4

// Per-head collapsed scalars, written by kernel A, read by kernel B.
// g_scal[h] = {A0, P, R, VA, VB} (A0,P,R already 1/sqrt(D)-scaled)
__device__ __align__(128) float g_scal[HH][8];

__device__ __forceinline__ float ex2f(float x) {
    float y;
    asm("ex2.approx.ftz.f32 %0, %1;" : "=f"(y) : "f"(x));
    return y;
}

// ---------------------------------------------------------------------------
// Kernel A: grid = 8 (one block per head), 512 threads = 16 warps.
// Warp w: matrix m = w&3 (0:kw 1:vw 2:vb 3:qv), row-quarter q = w>>2 (64 rows).
// Each warp: 64 coalesced matrix loads (one DRAM round-trip window) + shfl-fma.
// Finalize: warps 0..3 sum quarters (+bias); warp 0 forms the 5 head scalars.
// ---------------------------------------------------------------------------
__global__ void __launch_bounds__(512)
precompute_kernel(const float* __restrict__ emb_w,
                  const float* __restrict__ emb_b,
                  const float* __restrict__ q_w,
                  const float* __restrict__ q_b,
                  const float* __restrict__ k_w,
                  const float* __restrict__ v_w,
                  const float* __restrict__ v_b,
                  const float* __restrict__ attn_w) {
    __shared__ float s_pre[4][4][32];   // [matrix][quarter][lane]
    __shared__ float s_fin[4][32];      // finalized vectors

    const int h    = blockIdx.x;        // head == column group
    const int t    = threadIdx.x;
    const int warp = t >> 5;
    const int lane = t & 31;
    const int m    = warp & 3;          // 0:kw 1:vw 2:vb 3:qv
    const int q    = warp >> 2;         // row quarter 0..3
    const int col  = h * 32 + lane;

    const float* vecsrc = (m <= 1) ? emb_w : emb_b;
    const float* mat    = (m == 0) ? k_w : (m == 3 ? q_w : v_w);
    const float* mp     = mat + (q * 64) * EE + col;

    // this warp's 64 embedding entries (2 per lane)
    float ev0 = vecsrc[q * 64 +  0 + lane];
    float ev1 = vecsrc[q * 64 + 32 + lane];
    float bias = 0.f;
    if (q == 0) {
        if (m == 2) bias = v_b[col];
        if (m == 3) bias = q_b[col];
    }
    float aw = (warp == 0) ? attn_w[col] : 0.f;

    float a0 = 0.f, a1 = 0.f;
    #pragma unroll
    for (int e = 0; e < 32; e++) {
        a0 = fmaf(__shfl_sync(0xffffffffu, ev0, e), mp[(e     ) * EE], a0);
        a1 = fmaf(__shfl_sync(0xffffffffu, ev1, e), mp[(e + 32) * EE], a1);
    }
    s_pre[m][q][lane] = a0 + a1;
    __syncthreads();

    if (q == 0) {
        s_fin[m][lane] = (s_pre[m][0][lane] + s_pre[m][1][lane])
                       + (s_pre[m][2][lane] + s_pre[m][3][lane]) + bias;
    }
    __syncthreads();

    if (warp == 0) {
        float kw = s_fin[0][lane];
        float vw = s_fin[1][lane];
        float vb = s_fin[2][lane];
        float qv = s_fin[3][lane];

        const float scale = 0.17677669529663687f;   // 1/sqrt(32)
        float A0 = qv * kw, P = vw * kw, R = vb * kw, VA = vw * aw, VB = vb * aw;
        #pragma unroll
        for (int o = 16; o > 0; o >>= 1) {
            A0 += __shfl_xor_sync(0xffffffffu, A0, o);
            P  += __shfl_xor_sync(0xffffffffu, P,  o);
            R  += __shfl_xor_sync(0xffffffffu, R,  o);
            VA += __shfl_xor_sync(0xffffffffu, VA, o);
            VB += __shfl_xor_sync(0xffffffffu, VB, o);
        }
        if (lane == 0) {
            g_scal[h][0] = A0 * scale;
            g_scal[h][1] = P  * scale;
            g_scal[h][2] = R  * scale;
            g_scal[h][3] = VA;
            g_scal[h][4] = VB;
        }
    }
}

// ---------------------------------------------------------------------------
// Kernel B: grid = 64 (one block per batch), 256 threads = 8 warps = 8 heads.
// Warp h: full x_b[512] in registers (coalesced), max/min butterfly only on
// the critical path (sum butterfly deferred to the epilogue), then the L=4
// scalar softmax recursion from the 5 precomputed head scalars.
// ---------------------------------------------------------------------------
__global__ void __launch_bounds__(256, 8)
attn_kernel(const float* __restrict__ features,
            const float* __restrict__ attn_b,
            float* __restrict__ out) {
    __shared__ float s_ox[HH], s_hc[HH];

    const int b    = blockIdx.x;
    const int t    = threadIdx.x;
    const int warp = t >> 5;
    const int lane = t & 31;

    // ---- all loads issued up front ----
    const float* xb = features + b * FF;
    float xr[FF / 32];
    #pragma unroll
    for (int i = 0; i < FF / 32; i++) xr[i] = xb[lane + i * 32];

    float A0 = g_scal[warp][0];
    float P  = g_scal[warp][1];
    float R  = g_scal[warp][2];
    float VA = g_scal[warp][3];
    float VB = g_scal[warp][4];
    float ab = attn_b[0];

    // ---- critical-path stats: only max/min needed before iteration 1 ----
    float Sl = 0.f, xmax = -1e30f, xmin = 1e30f;
    #pragma unroll
    for (int i = 0; i < FF / 32; i++) {
        Sl += xr[i];
        xmax = fmaxf(xmax, xr[i]);
        xmin = fminf(xmin, xr[i]);
    }
    #pragma unroll
    for (int o = 16; o > 0; o >>= 1) {
        xmax = fmaxf(xmax, __shfl_xor_sync(0xffffffffu, xmax, o));
        xmin = fminf(xmin, __shfl_xor_sync(0xffffffffu, xmin, o));
    }

    // ---- L-step scalar softmax recursion (warp-local, tree sums) ----
    const float L2E = 1.4426950408889634f;
    float alpha = A0;
    float m = 0.f;
    #pragma unroll
    for (int it = 0; it < LL; it++) {
        float a2 = alpha * L2E;
        float M2 = (alpha >= 0.f) ? a2 * xmax : a2 * xmin;   // exact max logit
        float w[FF / 32];
        #pragma unroll
        for (int i = 0; i < FF / 32; i++) w[i] = ex2f(fmaf(a2, xr[i], -M2));
        float sw0 = w[0] + w[1],   sw1 = w[2] + w[3];
        float sw2 = w[4] + w[5],   sw3 = w[6] + w[7];
        float sw4 = w[8] + w[9],   sw5 = w[10] + w[11];
        float sw6 = w[12] + w[13], sw7 = w[14] + w[15];
        float sw = ((sw0 + sw1) + (sw2 + sw3)) + ((sw4 + sw5) + (sw6 + sw7));
        float t0 = fmaf(xr[1],  w[1],  xr[0]  * w[0]);
        float t1 = fmaf(xr[3],  w[3],  xr[2]  * w[2]);
        float t2 = fmaf(xr[5],  w[5],  xr[4]  * w[4]);
        float t3 = fmaf(xr[7],  w[7],  xr[6]  * w[6]);
        float t4 = fmaf(xr[9],  w[9],  xr[8]  * w[8]);
        float t5 = fmaf(xr[11], w[11], xr[10] * w[10]);
        float t6 = fmaf(xr[13], w[13], xr[12] * w[12]);
        float t7 = fmaf(xr[15], w[15], xr[14] * w[14]);
        float sxw = ((t0 + t1) + (t2 + t3)) + ((t4 + t5) + (t6 + t7));
        #pragma unroll
        for (int o = 16; o > 0; o >>= 1) {
            sw  += __shfl_xor_sync(0xffffffffu, sw,  o);
            sxw += __shfl_xor_sync(0xffffffffu, sxw, o);
        }
        m = __fdividef(sxw, sw);
        alpha = fmaf(m, P, R);
    }

    // ---- deferred sum butterfly (off the recursion path) ----
    float S = Sl;
    #pragma unroll
    for (int o = 16; o > 0; o >>= 1)
        S += __shfl_xor_sync(0xffffffffu, S, o);

    if (lane == 0) {
        s_ox[warp] = fmaf(m, VA, VB);                          // Qc contribution
        s_hc[warp] = fmaf(S - m, VA, (float)(FF - 1) * VB);    // (v_sum - Qc)
    }
    __syncthreads();   // single block sync

    float ox = ab, cc = ab;
    #pragma unroll
    for (int hh = 0; hh < HH; hh++) { ox += s_ox[hh]; cc += s_hc[hh]; }

    out[b * FF + t]                 = ox;
    out[b * FF + t + 256]           = ox;
    out[BB * FF + b * FF + t]       = cc;
    out[BB * FF + b * FF + t + 256] = cc;
}

extern "C" void kernel_launch(void* const* d_in, const int* in_sizes, int n_in,
                              void* d_out, int out_size) {
    const float* features = (const float*)d_in[0];
    const float* emb_w    = (const float*)d_in[1];
    const float* emb_b    = (const float*)d_in[2];
    const float* q_w      = (const float*)d_in[3];
    const float* q_b      = (const float*)d_in[4];
    const float* k_w      = (const float*)d_in[5];
    // d_in[6] = k_b: cancels in softmax, unused
    const float* v_w      = (const float*)d_in[7];
    const float* v_b      = (const float*)d_in[8];
    const float* attn_w   = (const float*)d_in[9];
    const float* attn_b   = (const float*)d_in[10];
    float* out = (float*)d_out;

    precompute_kernel<<<8, 512>>>(emb_w, emb_b, q_w, q_b, k_w, v_w, v_b, attn_w);
    attn_kernel<<<BB, 256>>>(features, attn_b, out);
}

// round 9
// speedup vs baseline: 1.0030x; 1.0030x over previous
#include <cuda_runtime.h>
#include <math.h>

#define BB 64
#define FF 512
#define EE 256
#define HH 8
#define DD 32
#define LL 4

// Partial column sums: [0]=kw [1]=vw [2]=vb [3]=qv, 16 row-slices each.
__device__ float g_part[4][16][EE];
// Per-head collapsed scalars {A0, P, R, VA, VB} (A0,P,R pre-scaled by 1/sqrt(D))
__device__ __align__(128) float g_scal[HH][8];
__device__ unsigned int g_cnt = 0;

__device__ __forceinline__ float ex2f(float x) {
    float y;
    asm("ex2.approx.ftz.f32 %0, %1;" : "=f"(y) : "f"(x));
    return y;
}

// ---------------------------------------------------------------------------
// Kernel A: grid = 48 (3 tasks x 16 row-slices), 256 threads (one per column).
//   task 0: kw += emb_w[r] * k_w[r][c]
//   task 1: vw += emb_w[r] * v_w[r][c]  AND  vb += emb_b[r] * v_w[r][c]
//           (dual accumulate: v_w is loaded ONCE for both outputs)
//   task 2: qv += emb_b[r] * q_w[r][c]
// Each block covers 16 rows -> 16 unrolled coalesced loads per thread.
// The last block to arrive (counter) sums the 16 partials per column,
// adds biases, and reduces to the 5 per-head scalars.
// ---------------------------------------------------------------------------
__global__ void __launch_bounds__(256)
precompute_kernel(const float* __restrict__ emb_w,
                  const float* __restrict__ emb_b,
                  const float* __restrict__ q_w,
                  const float* __restrict__ q_b,
                  const float* __restrict__ k_w,
                  const float* __restrict__ v_w,
                  const float* __restrict__ v_b,
                  const float* __restrict__ attn_w) {
    __shared__ unsigned int s_last;

    const int task  = blockIdx.x >> 4;    // 0,1,2
    const int slice = blockIdx.x & 15;    // row slice (16 rows)
    const int c     = threadIdx.x;        // output column 0..255
    const int r0    = slice * 16;

    if (task == 0) {
        const float* mp = k_w + r0 * EE + c;
        float acc = 0.f;
        #pragma unroll
        for (int i = 0; i < 16; i++) acc = fmaf(emb_w[r0 + i], mp[i * EE], acc);
        g_part[0][slice][c] = acc;
    } else if (task == 1) {
        const float* mp = v_w + r0 * EE + c;
        float accw = 0.f, accb = 0.f;
        #pragma unroll
        for (int i = 0; i < 16; i++) {
            float mv = mp[i * EE];
            accw = fmaf(emb_w[r0 + i], mv, accw);
            accb = fmaf(emb_b[r0 + i], mv, accb);
        }
        g_part[1][slice][c] = accw;
        g_part[2][slice][c] = accb;
    } else {
        const float* mp = q_w + r0 * EE + c;
        float acc = 0.f;
        #pragma unroll
        for (int i = 0; i < 16; i++) acc = fmaf(emb_b[r0 + i], mp[i * EE], acc);
        g_part[3][slice][c] = acc;
    }

    __threadfence();                      // release partials
    __syncthreads();
    if (c == 0) {
        unsigned int prev = atomicAdd(&g_cnt, 1u);
        s_last = (prev == 47u) ? 1u : 0u;
    }
    __syncthreads();
    if (s_last == 0u) return;

    // ---------------- finish (exactly one block reaches here) ----------------
    // L2-coherent reads of all partials (bypass possibly-stale L1).
    float kw = 0.f, vw = 0.f, vb = 0.f, qv = 0.f;
    #pragma unroll
    for (int s = 0; s < 16; s++) {
        kw += __ldcg(&g_part[0][s][c]);
        vw += __ldcg(&g_part[1][s][c]);
        vb += __ldcg(&g_part[2][s][c]);
        qv += __ldcg(&g_part[3][s][c]);
    }
    vb += v_b[c];
    qv += q_b[c];
    float aw = attn_w[c];

    const float scale = 0.17677669529663687f;   // 1/sqrt(32)
    float A0 = qv * kw, P = vw * kw, R = vb * kw, VA = vw * aw, VB = vb * aw;
    #pragma unroll
    for (int o = 16; o > 0; o >>= 1) {
        A0 += __shfl_xor_sync(0xffffffffu, A0, o);
        P  += __shfl_xor_sync(0xffffffffu, P,  o);
        R  += __shfl_xor_sync(0xffffffffu, R,  o);
        VA += __shfl_xor_sync(0xffffffffu, VA, o);
        VB += __shfl_xor_sync(0xffffffffu, VB, o);
    }
    const int lane = c & 31, h = c >> 5;
    if (lane == 0) {
        g_scal[h][0] = A0 * scale;
        g_scal[h][1] = P  * scale;
        g_scal[h][2] = R  * scale;
        g_scal[h][3] = VA;
        g_scal[h][4] = VB;
    }
    if (c == 0) g_cnt = 0u;               // reset for the next graph replay
}

// ---------------------------------------------------------------------------
// Kernel B: grid = 64 (one block per batch), 256 threads = 8 warps = 8 heads.
// Warp h: full x_b[512] in registers (coalesced), max/min butterfly on the
// critical path (sum deferred), then the L=4 scalar softmax recursion from
// the 5 precomputed head scalars (uniform-address loads).
// ---------------------------------------------------------------------------
__global__ void __launch_bounds__(256, 8)
attn_kernel(const float* __restrict__ features,
            const float* __restrict__ attn_b,
            float* __restrict__ out) {
    __shared__ float s_ox[HH], s_hc[HH];

    const int b    = blockIdx.x;
    const int t    = threadIdx.x;
    const int warp = t >> 5;
    const int lane = t & 31;

    // ---- all loads issued up front ----
    const float* xb = features + b * FF;
    float xr[FF / 32];
    #pragma unroll
    for (int i = 0; i < FF / 32; i++) xr[i] = xb[lane + i * 32];

    float A0 = g_scal[warp][0];
    float P  = g_scal[warp][1];
    float R  = g_scal[warp][2];
    float VA = g_scal[warp][3];
    float VB = g_scal[warp][4];
    float ab = attn_b[0];

    // ---- critical-path stats: only max/min needed before iteration 1 ----
    float Sl = 0.f, xmax = -1e30f, xmin = 1e30f;
    #pragma unroll
    for (int i = 0; i < FF / 32; i++) {
        Sl += xr[i];
        xmax = fmaxf(xmax, xr[i]);
        xmin = fminf(xmin, xr[i]);
    }
    #pragma unroll
    for (int o = 16; o > 0; o >>= 1) {
        xmax = fmaxf(xmax, __shfl_xor_sync(0xffffffffu, xmax, o));
        xmin = fminf(xmin, __shfl_xor_sync(0xffffffffu, xmin, o));
    }

    // ---- L-step scalar softmax recursion (warp-local, tree sums) ----
    const float L2E = 1.4426950408889634f;
    float alpha = A0;
    float m = 0.f;
    #pragma unroll
    for (int it = 0; it < LL; it++) {
        float a2 = alpha * L2E;
        float M2 = (alpha >= 0.f) ? a2 * xmax : a2 * xmin;   // exact max logit
        float w[FF / 32];
        #pragma unroll
        for (int i = 0; i < FF / 32; i++) w[i] = ex2f(fmaf(a2, xr[i], -M2));
        float sw0 = w[0] + w[1],   sw1 = w[2] + w[3];
        float sw2 = w[4] + w[5],   sw3 = w[6] + w[7];
        float sw4 = w[8] + w[9],   sw5 = w[10] + w[11];
        float sw6 = w[12] + w[13], sw7 = w[14] + w[15];
        float sw = ((sw0 + sw1) + (sw2 + sw3)) + ((sw4 + sw5) + (sw6 + sw7));
        float t0 = fmaf(xr[1],  w[1],  xr[0]  * w[0]);
        float t1 = fmaf(xr[3],  w[3],  xr[2]  * w[2]);
        float t2 = fmaf(xr[5],  w[5],  xr[4]  * w[4]);
        float t3 = fmaf(xr[7],  w[7],  xr[6]  * w[6]);
        float t4 = fmaf(xr[9],  w[9],  xr[8]  * w[8]);
        float t5 = fmaf(xr[11], w[11], xr[10] * w[10]);
        float t6 = fmaf(xr[13], w[13], xr[12] * w[12]);
        float t7 = fmaf(xr[15], w[15], xr[14] * w[14]);
        float sxw = ((t0 + t1) + (t2 + t3)) + ((t4 + t5) + (t6 + t7));
        #pragma unroll
        for (int o = 16; o > 0; o >>= 1) {
            sw  += __shfl_xor_sync(0xffffffffu, sw,  o);
            sxw += __shfl_xor_sync(0xffffffffu, sxw, o);
        }
        m = __fdividef(sxw, sw);
        alpha = fmaf(m, P, R);
    }

    // ---- deferred sum butterfly (off the recursion path) ----
    float S = Sl;
    #pragma unroll
    for (int o = 16; o > 0; o >>= 1)
        S += __shfl_xor_sync(0xffffffffu, S, o);

    if (lane == 0) {
        s_ox[warp] = fmaf(m, VA, VB);                          // Qc contribution
        s_hc[warp] = fmaf(S - m, VA, (float)(FF - 1) * VB);    // (v_sum - Qc)
    }
    __syncthreads();   // single block sync

    float ox = ab, cc = ab;
    #pragma unroll
    for (int hh = 0; hh < HH; hh++) { ox += s_ox[hh]; cc += s_hc[hh]; }

    out[b * FF + t]                 = ox;
    out[b * FF + t + 256]           = ox;
    out[BB * FF + b * FF + t]       = cc;
    out[BB * FF + b * FF + t + 256] = cc;
}

extern "C" void kernel_launch(void* const* d_in, const int* in_sizes, int n_in,
                              void* d_out, int out_size) {
    const float* features = (const float*)d_in[0];
    const float* emb_w    = (const float*)d_in[1];
    const float* emb_b    = (const float*)d_in[2];
    const float* q_w      = (const float*)d_in[3];
    const float* q_b      = (const float*)d_in[4];
    const float* k_w      = (const float*)d_in[5];
    // d_in[6] = k_b: cancels in softmax, unused
    const float* v_w      = (const float*)d_in[7];
    const float* v_b      = (const float*)d_in[8];
    const float* attn_w   = (const float*)d_in[9];
    const float* attn_b   = (const float*)d_in[10];
    float* out = (float*)d_out;

    precompute_kernel<<<48, 256>>>(emb_w, emb_b, q_w, q_b, k_w, v_w, v_b, attn_w);
    attn_kernel<<<BB, 256>>>(features, attn_b, out);
}